// round 14
// baseline (speedup 1.0000x reference)
#include <cuda_runtime.h>
#include <cuda_fp16.h>
#include <cuda_bf16.h>
#include <cstdint>

// ---------------------------------------------------------------------------
// TempoJelly R13: single-split fp16 HMMA GEMM + int8-digit candidate fixup.
//   s2 = ((x @ W1^T >= 1) @ W2^T >= 1), x binary.
//
//  Numerics identical to R11/R12 (rel_err 0.0): hi=fp16(w) GEMM split,
//  provable eps1 bound -> candidates -> dp4a int8-digit fixup -> exact fp32.
//
//  R13 change: GEMM retiled from 128 thr / 64x64 warp tiles (255 regs, 2
//  warps/SMSP, tensor=66.6%) to 256 thr / 8 warps of 64x(BN/4) (~125 regs,
//  4 warps/SMSP) to double latency hiding on the tensor pipe.
// ---------------------------------------------------------------------------

#define B_ROWS  4096
#define IN_K    3136
#define FEAT    6272
#define OUT_N   500
#define OUT_PAD 512
#define MAXC    (1 << 21)
#define MARGIN  3.0e-4f

// ---------------- static scratch --------------------------------------------
__device__ __align__(16) __half  g_xh  [(size_t)B_ROWS * IN_K];
__device__ __align__(16) int8_t  g_xi  [(size_t)B_ROWS * IN_K];
__device__ __align__(16) __half  g_w1h [(size_t)FEAT * IN_K];
__device__ __align__(16) int8_t  g_w1m [(size_t)FEAT * IN_K];
__device__ __align__(16) __half  g_w2h [(size_t)OUT_PAD * FEAT];
__device__ __align__(16) int8_t  g_w2m [(size_t)OUT_PAD * FEAT];
__device__ __align__(16) __half  g_s1h [(size_t)B_ROWS * FEAT];
__device__ __align__(16) int8_t  g_s1i [(size_t)B_ROWS * FEAT];
__device__ float g_e1a[FEAT],    g_e2a[FEAT],    g_is1[FEAT];
__device__ float g_e1b[OUT_PAD], g_e2b[OUT_PAD], g_is2[OUT_PAD];
__device__ uint32_t g_crc1[MAXC];
__device__ float    g_cv1 [MAXC];
__device__ uint32_t g_crc2[MAXC];
__device__ float    g_cv2 [MAXC];
__device__ uint32_t g_crc1e[MAXC];
__device__ uint32_t g_crc2e[MAXC];
__device__ uint32_t g_cnt[4];   // L1 cands, L1 final, L2 cands, L2 final

// ---------------- helpers ----------------------------------------------------
__device__ __forceinline__ uint32_t smem_u32(const void* p) {
    return (uint32_t)__cvta_generic_to_shared(p);
}
__device__ __forceinline__ uint32_t sw128(uint32_t off) {
    return off ^ ((off >> 3) & 0x70);
}
__device__ __forceinline__ int dp4a_s(uint32_t a, uint32_t b, int c) {
    return __dp4a((int)a, (int)b, c);
}

#define CP_ASYNC16(smaddr, gptr)                                               \
    asm volatile("cp.async.cg.shared.global [%0], [%1], 16;"                   \
                 :: "r"(smaddr), "l"(gptr))
#define CP_COMMIT() asm volatile("cp.async.commit_group;" ::: "memory")
#define CP_WAIT(n)  asm volatile("cp.async.wait_group %0;" :: "n"(n) : "memory")

#define LDSM_X4(r, addr)                                                       \
    asm volatile("ldmatrix.sync.aligned.m8n8.x4.shared.b16 {%0,%1,%2,%3}, [%4];" \
                 : "=r"((r)[0]), "=r"((r)[1]), "=r"((r)[2]), "=r"((r)[3])      \
                 : "r"(addr))

#define MMAF16(cc, aa, b0, b1)                                                 \
    asm volatile("mma.sync.aligned.m16n8k16.row.col.f32.f16.f16.f32 "          \
                 "{%0,%1,%2,%3},{%4,%5,%6,%7},{%8,%9},{%0,%1,%2,%3};"          \
                 : "+f"((cc)[0]), "+f"((cc)[1]), "+f"((cc)[2]), "+f"((cc)[3])  \
                 : "r"((aa)[0]), "r"((aa)[1]), "r"((aa)[2]), "r"((aa)[3]),     \
                   "r"(b0), "r"(b1))

// ---------------- prep kernels -----------------------------------------------
__global__ void cvt_x_kernel(const float* __restrict__ x,
                             __half* __restrict__ xh,
                             int8_t* __restrict__ xi) {
    if (blockIdx.x == 0 && threadIdx.x < 4) g_cnt[threadIdx.x] = 0;
    const size_t n4 = (size_t)B_ROWS * IN_K / 4;
    size_t i = (size_t)blockIdx.x * blockDim.x + threadIdx.x;
    const size_t stride = (size_t)gridDim.x * blockDim.x;
    for (; i < n4; i += stride) {
        const float4 v = reinterpret_cast<const float4*>(x)[i];
        const int b0 = (v.x != 0.0f), b1 = (v.y != 0.0f);
        const int b2 = (v.z != 0.0f), b3 = (v.w != 0.0f);
        const uint32_t h01 = (b0 ? 0x3C00u : 0u) | ((b1 ? 0x3C00u : 0u) << 16);
        const uint32_t h23 = (b2 ? 0x3C00u : 0u) | ((b3 ? 0x3C00u : 0u) << 16);
        reinterpret_cast<uint2*>(xh)[i] = make_uint2(h01, h23);
        reinterpret_cast<uchar4*>(xi)[i] =
            make_uchar4((unsigned char)b0, (unsigned char)b1,
                        (unsigned char)b2, (unsigned char)b3);
    }
}

__global__ void split_w_kernel(const float* __restrict__ W, int n_rows,
                               int rows_pad, int K,
                               __half* __restrict__ Wh,
                               int8_t* __restrict__ Wm,
                               float* __restrict__ e1,
                               float* __restrict__ e2,
                               float* __restrict__ invSo) {
    const int wid  = threadIdx.x >> 5;
    const int lane = threadIdx.x & 31;
    const int row  = blockIdx.x * (blockDim.x >> 5) + wid;
    if (row >= rows_pad) return;

    if (row >= n_rows) {
        for (int i = lane * 4; i < K; i += 128) {
            *reinterpret_cast<uint2*>(Wh + (size_t)row * K + i) = make_uint2(0, 0);
            *reinterpret_cast<char4*>(Wm + (size_t)row * K + i) = make_char4(0,0,0,0);
        }
        if (lane == 0) { e1[row] = -1.0f; e2[row] = -1.0f; invSo[row] = 0.0f; }
        return;
    }

    float s1 = 0.0f, mr = 0.0f;
    for (int i = lane * 4; i < K; i += 128) {
        const float4 v = *reinterpret_cast<const float4*>(W + (size_t)row * K + i);
        const float w[4] = {v.x, v.y, v.z, v.w};
        ushort hh[4];
#pragma unroll
        for (int j = 0; j < 4; j++) {
            const __half h = __float2half_rn(w[j]);
            const float r = w[j] - __half2float(h);
            s1 += fabsf(r);
            mr = fmaxf(mr, fabsf(r));
            hh[j] = __half_as_ushort(h);
        }
        *reinterpret_cast<uint2*>(Wh + (size_t)row * K + i) = make_uint2(
            (uint32_t)hh[0] | ((uint32_t)hh[1] << 16),
            (uint32_t)hh[2] | ((uint32_t)hh[3] << 16));
    }
#pragma unroll
    for (int o = 16; o; o >>= 1) {
        s1 += __shfl_xor_sync(~0u, s1, o);
        mr = fmaxf(mr, __shfl_xor_sync(~0u, mr, o));
    }
    const float S    = (mr > 0.0f) ? (127.0f / mr) : 1.0f;
    const float invS = (mr > 0.0f) ? (mr / 127.0f) : 0.0f;

    float s2 = 0.0f;
    for (int i = lane * 4; i < K; i += 128) {
        const float4 v = *reinterpret_cast<const float4*>(W + (size_t)row * K + i);
        const float w[4] = {v.x, v.y, v.z, v.w};
        char mm[4];
#pragma unroll
        for (int j = 0; j < 4; j++) {
            const __half h = __float2half_rn(w[j]);
            const float r = w[j] - __half2float(h);
            int q = __float2int_rn(r * S);
            q = max(-127, min(127, q));
            s2 += fabsf(fmaf(-(float)q, invS, r));
            mm[j] = (char)q;
        }
        *reinterpret_cast<char4*>(Wm + (size_t)row * K + i) =
            make_char4(mm[0], mm[1], mm[2], mm[3]);
    }
#pragma unroll
    for (int o = 16; o; o >>= 1) s2 += __shfl_xor_sync(~0u, s2, o);
    if (lane == 0) {
        e1[row] = s1 + MARGIN;
        e2[row] = s2 + MARGIN;
        invSo[row] = invS;
    }
}

// ---------------- fp16 HMMA GEMM: CTA 128xBN, 256 thr, 8 warps, 3 stages ------
// Warp grid 2 (M) x 4 (N): warp tile 64 x (BN/4).
// BN=128: warp tile 64x32, NB=2; BN=64: warp tile 64x16, NB=1.
template <int BN>
__global__ __launch_bounds__(256, 2)
void spike_gemm_f16(const __half* __restrict__ A,
                    const __half* __restrict__ B,
                    const float* __restrict__ eps1,
                    __half* __restrict__ outH,       // dual-mode (layer 1)
                    int8_t* __restrict__ outI,
                    float* __restrict__ outF,        // fp32-mode (layer 2)
                    uint32_t* __restrict__ cand_rc,
                    float* __restrict__ cand_val,
                    uint32_t* __restrict__ cnt,
                    int K, int Nstride, int Nstore) {
    constexpr int WN = BN / 4;                   // warp tile N
    constexpr int NB = WN / 16;                  // 16-col groups per warp
    constexpr int STAGE = 16384 + BN * 128;
    constexpr int NSTG = 3;

    extern __shared__ char smem[];
    const uint32_t sbase = smem_u32(smem);
    const uint32_t data0 = (sbase + 1023u) & ~1023u;

    const int tid  = threadIdx.x;
    const int lane = tid & 31;
    const int wid  = tid >> 5;
    const int wm   = wid & 1;           // 2 warp-rows x 64
    const int wn   = wid >> 1;          // 4 warp-cols x WN
    const int bm   = blockIdx.y * 128;
    const int bn   = blockIdx.x * BN;
    const int K8   = K >> 3;
    const int nchunks = K >> 6;

    const int rA = lane & 15;
    const int kA = (lane >> 4) * 16;
    const int rB = ((lane >> 4) << 3) | (lane & 7);
    const int kB = ((lane >> 3) & 1) * 16;

    float acc[4][NB][8];
#pragma unroll
    for (int mt = 0; mt < 4; mt++)
#pragma unroll
        for (int nb = 0; nb < NB; nb++)
#pragma unroll
            for (int r = 0; r < 8; r++) acc[mt][nb][r] = 0.0f;

    auto load_chunk = [&](int ch) {
        uint32_t buf = data0 + (uint32_t)(ch % NSTG) * STAGE;
        const int k0u = ch << 3;
#pragma unroll
        for (int t = 0; t < 4; ++t) {            // A: 1024 uint4 / 256 thr
            const int u = tid + t * 256;
            const int row = u >> 3, ku = u & 7;
            const uint4* src = reinterpret_cast<const uint4*>(A)
                             + (size_t)(bm + row) * K8 + k0u + ku;
            CP_ASYNC16(buf + sw128(row * 128 + ku * 16), src);
        }
#pragma unroll
        for (int t = 0; t < BN / 32; ++t) {      // B: BN*8 uint4 / 256 thr
            const int u = tid + t * 256;
            const int row = u >> 3, ku = u & 7;
            const uint4* src = reinterpret_cast<const uint4*>(B)
                             + (size_t)(bn + row) * K8 + k0u + ku;
            CP_ASYNC16(buf + 16384u + sw128(row * 128 + ku * 16), src);
        }
        CP_COMMIT();
    };

    load_chunk(0);
    load_chunk(1);

    for (int ch = 0; ch < nchunks; ++ch) {
        CP_WAIT(1);
        __syncthreads();

        if (ch + 2 < nchunks) load_chunk(ch + 2);
        else CP_COMMIT();

        const uint32_t buf = data0 + (uint32_t)(ch % NSTG) * STAGE;
#pragma unroll
        for (int ks = 0; ks < 4; ++ks) {
            uint32_t a[4][4];
#pragma unroll
            for (int mt = 0; mt < 4; mt++) {
                const uint32_t addr = buf
                    + sw128((wm * 64 + mt * 16 + rA) * 128 + ks * 32 + kA);
                LDSM_X4(a[mt], addr);
            }
#pragma unroll
            for (int nb = 0; nb < NB; nb++) {
                uint32_t b[4];
                const uint32_t addr = buf + 16384u
                    + sw128((wn * WN + nb * 16 + rB) * 128 + ks * 32 + kB);
                LDSM_X4(b, addr);
#pragma unroll
                for (int mt = 0; mt < 4; mt++) {
                    MMAF16(acc[mt][nb] + 0, a[mt], b[0], b[1]);
                    MMAF16(acc[mt][nb] + 4, a[mt], b[2], b[3]);
                }
            }
        }
    }

    // ---- epilogue: threshold + candidate capture ----
    float ev[NB][2][2];
#pragma unroll
    for (int nb = 0; nb < NB; nb++)
#pragma unroll
        for (int h = 0; h < 2; h++) {
            const int col = bn + wn * WN + nb * 16 + h * 8 + (lane & 3) * 2;
            ev[nb][h][0] = eps1[col];
            ev[nb][h][1] = eps1[col + 1];
        }

#pragma unroll
    for (int mt = 0; mt < 4; mt++) {
        const int row0 = bm + wm * 64 + mt * 16 + (lane >> 2);
#pragma unroll
        for (int nb = 0; nb < NB; nb++) {
#pragma unroll
            for (int h = 0; h < 2; h++) {
                const int col = bn + wn * WN + nb * 16 + h * 8 + (lane & 3) * 2;
                const float* v = acc[mt][nb] + h * 4;
                int sp[4];
#pragma unroll
                for (int r = 0; r < 4; r++) {
                    sp[r] = (v[r] >= 1.0f);
                    const int colr = col + (r & 1);
                    if (fabsf(v[r] - 1.0f) <= ev[nb][h][r & 1] && colr < Nstore) {
                        const int rowr = row0 + (r >> 1) * 8;
                        const uint32_t idx = atomicAdd(cnt, 1u);
                        if (idx < MAXC) {
                            cand_rc[idx]  = ((uint32_t)rowr << 16) | (uint32_t)colr;
                            cand_val[idx] = v[r];
                        }
                    }
                }
                if (outF == nullptr) {
                    *reinterpret_cast<uint32_t*>(
                        outH + (size_t)row0 * Nstride + col) =
                        (sp[0] ? 0x3C00u : 0u) | ((sp[1] ? 0x3C00u : 0u) << 16);
                    *reinterpret_cast<uint32_t*>(
                        outH + (size_t)(row0 + 8) * Nstride + col) =
                        (sp[2] ? 0x3C00u : 0u) | ((sp[3] ? 0x3C00u : 0u) << 16);
                    *reinterpret_cast<uint16_t*>(
                        outI + (size_t)row0 * Nstride + col) =
                        (uint16_t)(sp[0] | (sp[1] << 8));
                    *reinterpret_cast<uint16_t*>(
                        outI + (size_t)(row0 + 8) * Nstride + col) =
                        (uint16_t)(sp[2] | (sp[3] << 8));
                } else if (col < Nstore) {
                    *reinterpret_cast<float2*>(
                        outF + (size_t)row0 * Nstore + col) =
                        make_float2((float)sp[0], (float)sp[1]);
                    *reinterpret_cast<float2*>(
                        outF + (size_t)(row0 + 8) * Nstore + col) =
                        make_float2((float)sp[2], (float)sp[3]);
                }
            }
        }
    }
}

// ---------------- fixup 1: int8-digit dot via dp4a ---------------------------
__global__ void fixmid_kernel(const uint32_t* __restrict__ crc,
                              const float* __restrict__ cval,
                              const uint32_t* __restrict__ cntp,
                              const int8_t* __restrict__ X,
                              const int8_t* __restrict__ Wm,
                              const float* __restrict__ e2,
                              const float* __restrict__ invS,
                              int K,
                              __half* __restrict__ outH,
                              int8_t* __restrict__ outI,
                              float* __restrict__ outF,
                              int NstrideH, int NstrideF,
                              uint32_t* __restrict__ crc_e,
                              uint32_t* __restrict__ cnt_e) {
    const int gw   = (blockIdx.x * blockDim.x + threadIdx.x) >> 5;
    const int lane = threadIdx.x & 31;
    const int nw   = (gridDim.x * blockDim.x) >> 5;
    uint32_t n = *cntp; if (n > MAXC) n = MAXC;
    const int K16 = K >> 4;
    for (uint32_t i = gw; i < n; i += nw) {
        const uint32_t e = crc[i];
        const int row = (int)(e >> 16);
        const int col = (int)(e & 0xFFFFu);
        int sc = 0;
        const uint4* xr = reinterpret_cast<const uint4*>(X)  + (size_t)row * K16;
        const uint4* mr = reinterpret_cast<const uint4*>(Wm) + (size_t)col * K16;
        for (int u = lane; u < K16; u += 32) {
            const uint4 xv = xr[u];
            const uint4 mv = mr[u];
            sc = dp4a_s(xv.x, mv.x, sc);
            sc = dp4a_s(xv.y, mv.y, sc);
            sc = dp4a_s(xv.z, mv.z, sc);
            sc = dp4a_s(xv.w, mv.w, sc);
        }
#pragma unroll
        for (int o = 16; o; o >>= 1) sc += __shfl_xor_sync(~0u, sc, o);
        if (lane == 0) {
            const float t = cval[i] + (float)sc * invS[col];
            if (fabsf(t - 1.0f) <= e2[col]) {
                const uint32_t idx = atomicAdd(cnt_e, 1u);
                if (idx < MAXC) crc_e[idx] = e;
            } else {
                const int spike = (t >= 1.0f);
                if (outF == nullptr) {
                    outH[(size_t)row * NstrideH + col] =
                        __ushort_as_half(spike ? (ushort)0x3C00 : (ushort)0);
                    outI[(size_t)row * NstrideH + col] = (int8_t)spike;
                } else {
                    outF[(size_t)row * NstrideF + col] = (float)spike;
                }
            }
        }
    }
}

// ---------------- fixup 2: exact fp32 dot -------------------------------------
__global__ void fixe_kernel(const uint32_t* __restrict__ crc,
                            const uint32_t* __restrict__ cntp,
                            const int8_t* __restrict__ X,
                            const float* __restrict__ W, int K,
                            __half* __restrict__ outH,
                            int8_t* __restrict__ outI,
                            float* __restrict__ outF,
                            int NstrideH, int NstrideF) {
    const int gw   = (blockIdx.x * blockDim.x + threadIdx.x) >> 5;
    const int lane = threadIdx.x & 31;
    const int nw   = (gridDim.x * blockDim.x) >> 5;
    uint32_t n = *cntp; if (n > MAXC) n = MAXC;
    for (uint32_t i = gw; i < n; i += nw) {
        const uint32_t e = crc[i];
        const int row = (int)(e >> 16);
        const int col = (int)(e & 0xFFFFu);
        float s = 0.0f;
        for (int k = lane; k < K; k += 32)
            s += (float)X[(size_t)row * K + k] * W[(size_t)col * K + k];
#pragma unroll
        for (int o = 16; o; o >>= 1) s += __shfl_xor_sync(~0u, s, o);
        if (lane == 0) {
            const int spike = (s >= 1.0f);
            if (outF == nullptr) {
                outH[(size_t)row * NstrideH + col] =
                    __ushort_as_half(spike ? (ushort)0x3C00 : (ushort)0);
                outI[(size_t)row * NstrideH + col] = (int8_t)spike;
            } else {
                outF[(size_t)row * NstrideF + col] = (float)spike;
            }
        }
    }
}

// ---------------- host launch --------------------------------------------------
extern "C" void kernel_launch(void* const* d_in, const int* in_sizes, int n_in,
                              void* d_out, int out_size) {
    const float* x  = (const float*)d_in[0];
    const float* W1 = (const float*)d_in[1];
    const float* W2 = (const float*)d_in[2];
    float* out = (float*)d_out;

    __half *xh, *w1h, *w2h, *s1h;
    int8_t *xi, *w1m, *w2m, *s1i;
    float *e1a, *e2a, *is1, *e1b, *e2b, *is2, *cv1, *cv2;
    uint32_t *crc1, *crc2, *crc1e, *crc2e, *cnt;
    cudaGetSymbolAddress((void**)&xh,  g_xh);
    cudaGetSymbolAddress((void**)&xi,  g_xi);
    cudaGetSymbolAddress((void**)&w1h, g_w1h);
    cudaGetSymbolAddress((void**)&w1m, g_w1m);
    cudaGetSymbolAddress((void**)&w2h, g_w2h);
    cudaGetSymbolAddress((void**)&w2m, g_w2m);
    cudaGetSymbolAddress((void**)&s1h, g_s1h);
    cudaGetSymbolAddress((void**)&s1i, g_s1i);
    cudaGetSymbolAddress((void**)&e1a, g_e1a);
    cudaGetSymbolAddress((void**)&e2a, g_e2a);
    cudaGetSymbolAddress((void**)&is1, g_is1);
    cudaGetSymbolAddress((void**)&e1b, g_e1b);
    cudaGetSymbolAddress((void**)&e2b, g_e2b);
    cudaGetSymbolAddress((void**)&is2, g_is2);
    cudaGetSymbolAddress((void**)&crc1,  g_crc1);
    cudaGetSymbolAddress((void**)&cv1,   g_cv1);
    cudaGetSymbolAddress((void**)&crc2,  g_crc2);
    cudaGetSymbolAddress((void**)&cv2,   g_cv2);
    cudaGetSymbolAddress((void**)&crc1e, g_crc1e);
    cudaGetSymbolAddress((void**)&crc2e, g_crc2e);
    cudaGetSymbolAddress((void**)&cnt,   g_cnt);

    const int smem1 = 1024 + 3 * (16384 + 128 * 128);   // BN=128: 99328
    const int smem2 = 1024 + 3 * (16384 + 64 * 128);    // BN= 64: 74752
    cudaFuncSetAttribute(spike_gemm_f16<128>,
                         cudaFuncAttributeMaxDynamicSharedMemorySize, smem1);
    cudaFuncSetAttribute(spike_gemm_f16<64>,
                         cudaFuncAttributeMaxDynamicSharedMemorySize, smem2);

    cvt_x_kernel<<<2048, 256>>>(x, xh, xi);   // also resets g_cnt
    split_w_kernel<<<FEAT / 8, 256>>>(W1, FEAT, FEAT, IN_K,
                                      w1h, w1m, e1a, e2a, is1);
    split_w_kernel<<<OUT_PAD / 8, 256>>>(W2, OUT_N, OUT_PAD, FEAT,
                                         w2h, w2m, e1b, e2b, is2);

    // Layer 1: s1 = (x @ W1^T >= 1)  -> dual fp16 + int8   (BN=128)
    {
        dim3 grid(FEAT / 128, B_ROWS / 128);   // (49, 32)
        spike_gemm_f16<128><<<grid, 256, smem1>>>(
            xh, w1h, e1a, s1h, s1i, nullptr,
            crc1, cv1, cnt + 0, IN_K, FEAT, FEAT);
    }
    fixmid_kernel<<<1024, 256>>>(crc1, cv1, cnt + 0, xi, w1m, e2a, is1, IN_K,
                                 s1h, s1i, nullptr, FEAT, 0, crc1e, cnt + 1);
    fixe_kernel<<<512, 256>>>(crc1e, cnt + 1, xi, W1, IN_K,
                              s1h, s1i, nullptr, FEAT, 0);

    // Layer 2: out = (s1 @ W2^T >= 1)  -> fp32   (BN=64, 256 CTAs = 1 wave)
    {
        dim3 grid(OUT_PAD / 64, B_ROWS / 128);  // (8, 32)
        spike_gemm_f16<64><<<grid, 256, smem2>>>(
            s1h, w2h, e1b, nullptr, nullptr, out,
            crc2, cv2, cnt + 2, FEAT, OUT_N, OUT_N);
    }
    fixmid_kernel<<<1024, 256>>>(crc2, cv2, cnt + 2, s1i, w2m, e2b, is2, FEAT,
                                 nullptr, nullptr, out, 0, OUT_N, crc2e, cnt + 3);
    fixe_kernel<<<512, 256>>>(crc2e, cnt + 3, s1i, W2, FEAT,
                              nullptr, nullptr, out, 0, OUT_N);
}

// round 15
// speedup vs baseline: 1.0475x; 1.0475x over previous
#include <cuda_runtime.h>
#include <cuda_fp16.h>
#include <cuda_bf16.h>
#include <cstdint>

// ---------------------------------------------------------------------------
// TempoJelly R15: single-split fp16 HMMA GEMM + int8-digit candidate fixup.
//   s2 = ((x @ W1^T >= 1) @ W2^T >= 1), x binary.
//
//  Numerics identical to R11/R12 (rel_err 0.0).
//  GEMM shape reverted to R12 (128 thr, 2x2 warps of 64x(BN/2), 3-stage) --
//  the 256-thr R13 retile regressed (2x redundant A-LDSM traffic).
//  R15 change: ks-level operand-fragment double buffering (prefetch ks+1's
//  ldmatrix fragments before issuing ks's MMAs) to hide LDS latency.
// ---------------------------------------------------------------------------

#define B_ROWS  4096
#define IN_K    3136
#define FEAT    6272
#define OUT_N   500
#define OUT_PAD 512
#define MAXC    (1 << 21)
#define MARGIN  3.0e-4f

// ---------------- static scratch --------------------------------------------
__device__ __align__(16) __half  g_xh  [(size_t)B_ROWS * IN_K];
__device__ __align__(16) int8_t  g_xi  [(size_t)B_ROWS * IN_K];
__device__ __align__(16) __half  g_w1h [(size_t)FEAT * IN_K];
__device__ __align__(16) int8_t  g_w1m [(size_t)FEAT * IN_K];
__device__ __align__(16) __half  g_w2h [(size_t)OUT_PAD * FEAT];
__device__ __align__(16) int8_t  g_w2m [(size_t)OUT_PAD * FEAT];
__device__ __align__(16) __half  g_s1h [(size_t)B_ROWS * FEAT];
__device__ __align__(16) int8_t  g_s1i [(size_t)B_ROWS * FEAT];
__device__ float g_e1a[FEAT],    g_e2a[FEAT],    g_is1[FEAT];
__device__ float g_e1b[OUT_PAD], g_e2b[OUT_PAD], g_is2[OUT_PAD];
__device__ uint32_t g_crc1[MAXC];
__device__ float    g_cv1 [MAXC];
__device__ uint32_t g_crc2[MAXC];
__device__ float    g_cv2 [MAXC];
__device__ uint32_t g_crc1e[MAXC];
__device__ uint32_t g_crc2e[MAXC];
__device__ uint32_t g_cnt[4];   // L1 cands, L1 final, L2 cands, L2 final

// ---------------- helpers ----------------------------------------------------
__device__ __forceinline__ uint32_t smem_u32(const void* p) {
    return (uint32_t)__cvta_generic_to_shared(p);
}
__device__ __forceinline__ uint32_t sw128(uint32_t off) {
    return off ^ ((off >> 3) & 0x70);
}
__device__ __forceinline__ int dp4a_s(uint32_t a, uint32_t b, int c) {
    return __dp4a((int)a, (int)b, c);
}

#define CP_ASYNC16(smaddr, gptr)                                               \
    asm volatile("cp.async.cg.shared.global [%0], [%1], 16;"                   \
                 :: "r"(smaddr), "l"(gptr))
#define CP_COMMIT() asm volatile("cp.async.commit_group;" ::: "memory")
#define CP_WAIT(n)  asm volatile("cp.async.wait_group %0;" :: "n"(n) : "memory")

#define LDSM_X4(r, addr)                                                       \
    asm volatile("ldmatrix.sync.aligned.m8n8.x4.shared.b16 {%0,%1,%2,%3}, [%4];" \
                 : "=r"((r)[0]), "=r"((r)[1]), "=r"((r)[2]), "=r"((r)[3])      \
                 : "r"(addr))

#define MMAF16(cc, aa, b0, b1)                                                 \
    asm volatile("mma.sync.aligned.m16n8k16.row.col.f32.f16.f16.f32 "          \
                 "{%0,%1,%2,%3},{%4,%5,%6,%7},{%8,%9},{%0,%1,%2,%3};"          \
                 : "+f"((cc)[0]), "+f"((cc)[1]), "+f"((cc)[2]), "+f"((cc)[3])  \
                 : "r"((aa)[0]), "r"((aa)[1]), "r"((aa)[2]), "r"((aa)[3]),     \
                   "r"(b0), "r"(b1))

// ---------------- prep kernels -----------------------------------------------
__global__ void cvt_x_kernel(const float* __restrict__ x,
                             __half* __restrict__ xh,
                             int8_t* __restrict__ xi) {
    if (blockIdx.x == 0 && threadIdx.x < 4) g_cnt[threadIdx.x] = 0;
    const size_t n4 = (size_t)B_ROWS * IN_K / 4;
    size_t i = (size_t)blockIdx.x * blockDim.x + threadIdx.x;
    const size_t stride = (size_t)gridDim.x * blockDim.x;
    for (; i < n4; i += stride) {
        const float4 v = reinterpret_cast<const float4*>(x)[i];
        const int b0 = (v.x != 0.0f), b1 = (v.y != 0.0f);
        const int b2 = (v.z != 0.0f), b3 = (v.w != 0.0f);
        const uint32_t h01 = (b0 ? 0x3C00u : 0u) | ((b1 ? 0x3C00u : 0u) << 16);
        const uint32_t h23 = (b2 ? 0x3C00u : 0u) | ((b3 ? 0x3C00u : 0u) << 16);
        reinterpret_cast<uint2*>(xh)[i] = make_uint2(h01, h23);
        reinterpret_cast<uchar4*>(xi)[i] =
            make_uchar4((unsigned char)b0, (unsigned char)b1,
                        (unsigned char)b2, (unsigned char)b3);
    }
}

__global__ void split_w_kernel(const float* __restrict__ W, int n_rows,
                               int rows_pad, int K,
                               __half* __restrict__ Wh,
                               int8_t* __restrict__ Wm,
                               float* __restrict__ e1,
                               float* __restrict__ e2,
                               float* __restrict__ invSo) {
    const int wid  = threadIdx.x >> 5;
    const int lane = threadIdx.x & 31;
    const int row  = blockIdx.x * (blockDim.x >> 5) + wid;
    if (row >= rows_pad) return;

    if (row >= n_rows) {
        for (int i = lane * 4; i < K; i += 128) {
            *reinterpret_cast<uint2*>(Wh + (size_t)row * K + i) = make_uint2(0, 0);
            *reinterpret_cast<char4*>(Wm + (size_t)row * K + i) = make_char4(0,0,0,0);
        }
        if (lane == 0) { e1[row] = -1.0f; e2[row] = -1.0f; invSo[row] = 0.0f; }
        return;
    }

    float s1 = 0.0f, mr = 0.0f;
    for (int i = lane * 4; i < K; i += 128) {
        const float4 v = *reinterpret_cast<const float4*>(W + (size_t)row * K + i);
        const float w[4] = {v.x, v.y, v.z, v.w};
        ushort hh[4];
#pragma unroll
        for (int j = 0; j < 4; j++) {
            const __half h = __float2half_rn(w[j]);
            const float r = w[j] - __half2float(h);
            s1 += fabsf(r);
            mr = fmaxf(mr, fabsf(r));
            hh[j] = __half_as_ushort(h);
        }
        *reinterpret_cast<uint2*>(Wh + (size_t)row * K + i) = make_uint2(
            (uint32_t)hh[0] | ((uint32_t)hh[1] << 16),
            (uint32_t)hh[2] | ((uint32_t)hh[3] << 16));
    }
#pragma unroll
    for (int o = 16; o; o >>= 1) {
        s1 += __shfl_xor_sync(~0u, s1, o);
        mr = fmaxf(mr, __shfl_xor_sync(~0u, mr, o));
    }
    const float S    = (mr > 0.0f) ? (127.0f / mr) : 1.0f;
    const float invS = (mr > 0.0f) ? (mr / 127.0f) : 0.0f;

    float s2 = 0.0f;
    for (int i = lane * 4; i < K; i += 128) {
        const float4 v = *reinterpret_cast<const float4*>(W + (size_t)row * K + i);
        const float w[4] = {v.x, v.y, v.z, v.w};
        char mm[4];
#pragma unroll
        for (int j = 0; j < 4; j++) {
            const __half h = __float2half_rn(w[j]);
            const float r = w[j] - __half2float(h);
            int q = __float2int_rn(r * S);
            q = max(-127, min(127, q));
            s2 += fabsf(fmaf(-(float)q, invS, r));
            mm[j] = (char)q;
        }
        *reinterpret_cast<char4*>(Wm + (size_t)row * K + i) =
            make_char4(mm[0], mm[1], mm[2], mm[3]);
    }
#pragma unroll
    for (int o = 16; o; o >>= 1) s2 += __shfl_xor_sync(~0u, s2, o);
    if (lane == 0) {
        e1[row] = s1 + MARGIN;
        e2[row] = s2 + MARGIN;
        invSo[row] = invS;
    }
}

// ---------------- fp16 HMMA GEMM: CTA 128xBN, 128 thr, 2x2 warps, 3 stages ----
// Warp tile 64 x (BN/2). Fragment double-buffering across the 4 ks steps.
template <int BN>
__global__ __launch_bounds__(128, 2)
void spike_gemm_f16(const __half* __restrict__ A,
                    const __half* __restrict__ B,
                    const float* __restrict__ eps1,
                    __half* __restrict__ outH,       // dual-mode (layer 1)
                    int8_t* __restrict__ outI,
                    float* __restrict__ outF,        // fp32-mode (layer 2)
                    uint32_t* __restrict__ cand_rc,
                    float* __restrict__ cand_val,
                    uint32_t* __restrict__ cnt,
                    int K, int Nstride, int Nstore) {
    constexpr int WN = BN / 2;                   // warp tile N
    constexpr int NB = WN / 16;                  // 16-col groups per warp
    constexpr int STAGE = 16384 + BN * 128;
    constexpr int NSTG = 3;

    extern __shared__ char smem[];
    const uint32_t sbase = smem_u32(smem);
    const uint32_t data0 = (sbase + 1023u) & ~1023u;

    const int tid  = threadIdx.x;
    const int lane = tid & 31;
    const int wid  = tid >> 5;
    const int wm   = wid & 1;           // 2 warp-rows x 64
    const int wn   = wid >> 1;          // 2 warp-cols x WN
    const int bm   = blockIdx.y * 128;
    const int bn   = blockIdx.x * BN;
    const int K8   = K >> 3;
    const int nchunks = K >> 6;

    const int rA = lane & 15;
    const int kA = (lane >> 4) * 16;
    const int rB = ((lane >> 4) << 3) | (lane & 7);
    const int kB = ((lane >> 3) & 1) * 16;

    float acc[4][NB][8];
#pragma unroll
    for (int mt = 0; mt < 4; mt++)
#pragma unroll
        for (int nb = 0; nb < NB; nb++)
#pragma unroll
            for (int r = 0; r < 8; r++) acc[mt][nb][r] = 0.0f;

    auto load_chunk = [&](int ch) {
        uint32_t buf = data0 + (uint32_t)(ch % NSTG) * STAGE;
        const int k0u = ch << 3;
#pragma unroll
        for (int t = 0; t < 8; ++t) {            // A: 1024 uint4 / 128 thr
            const int u = tid + t * 128;
            const int row = u >> 3, ku = u & 7;
            const uint4* src = reinterpret_cast<const uint4*>(A)
                             + (size_t)(bm + row) * K8 + k0u + ku;
            CP_ASYNC16(buf + sw128(row * 128 + ku * 16), src);
        }
#pragma unroll
        for (int t = 0; t < BN / 16; ++t) {      // B: BN*8 uint4 / 128 thr
            const int u = tid + t * 128;
            const int row = u >> 3, ku = u & 7;
            const uint4* src = reinterpret_cast<const uint4*>(B)
                             + (size_t)(bn + row) * K8 + k0u + ku;
            CP_ASYNC16(buf + 16384u + sw128(row * 128 + ku * 16), src);
        }
        CP_COMMIT();
    };

    load_chunk(0);
    load_chunk(1);

    // fragment ping-pong buffers
    uint32_t afr[2][4][4];
    uint32_t bfr[2][NB][4];

    for (int ch = 0; ch < nchunks; ++ch) {
        CP_WAIT(1);
        __syncthreads();

        if (ch + 2 < nchunks) load_chunk(ch + 2);
        else CP_COMMIT();

        const uint32_t buf = data0 + (uint32_t)(ch % NSTG) * STAGE;

        // prime ks=0 fragments
#pragma unroll
        for (int mt = 0; mt < 4; mt++) {
            LDSM_X4(afr[0][mt],
                    buf + sw128((wm * 64 + mt * 16 + rA) * 128 + kA));
        }
#pragma unroll
        for (int nb = 0; nb < NB; nb++) {
            LDSM_X4(bfr[0][nb],
                    buf + 16384u + sw128((wn * WN + nb * 16 + rB) * 128 + kB));
        }

#pragma unroll
        for (int ks = 0; ks < 4; ++ks) {
            const int cur = ks & 1;
            const int nxt = cur ^ 1;
            if (ks < 3) {   // prefetch ks+1 fragments before MMAs
#pragma unroll
                for (int mt = 0; mt < 4; mt++) {
                    LDSM_X4(afr[nxt][mt],
                            buf + sw128((wm * 64 + mt * 16 + rA) * 128
                                        + (ks + 1) * 32 + kA));
                }
#pragma unroll
                for (int nb = 0; nb < NB; nb++) {
                    LDSM_X4(bfr[nxt][nb],
                            buf + 16384u + sw128((wn * WN + nb * 16 + rB) * 128
                                                 + (ks + 1) * 32 + kB));
                }
            }
#pragma unroll
            for (int nb = 0; nb < NB; nb++) {
#pragma unroll
                for (int mt = 0; mt < 4; mt++) {
                    MMAF16(acc[mt][nb] + 0, afr[cur][mt],
                           bfr[cur][nb][0], bfr[cur][nb][1]);
                    MMAF16(acc[mt][nb] + 4, afr[cur][mt],
                           bfr[cur][nb][2], bfr[cur][nb][3]);
                }
            }
        }
    }

    // ---- epilogue: threshold + candidate capture ----
    float ev[NB][2][2];
#pragma unroll
    for (int nb = 0; nb < NB; nb++)
#pragma unroll
        for (int h = 0; h < 2; h++) {
            const int col = bn + wn * WN + nb * 16 + h * 8 + (lane & 3) * 2;
            ev[nb][h][0] = eps1[col];
            ev[nb][h][1] = eps1[col + 1];
        }

#pragma unroll
    for (int mt = 0; mt < 4; mt++) {
        const int row0 = bm + wm * 64 + mt * 16 + (lane >> 2);
#pragma unroll
        for (int nb = 0; nb < NB; nb++) {
#pragma unroll
            for (int h = 0; h < 2; h++) {
                const int col = bn + wn * WN + nb * 16 + h * 8 + (lane & 3) * 2;
                const float* v = acc[mt][nb] + h * 4;
                int sp[4];
#pragma unroll
                for (int r = 0; r < 4; r++) {
                    sp[r] = (v[r] >= 1.0f);
                    const int colr = col + (r & 1);
                    if (fabsf(v[r] - 1.0f) <= ev[nb][h][r & 1] && colr < Nstore) {
                        const int rowr = row0 + (r >> 1) * 8;
                        const uint32_t idx = atomicAdd(cnt, 1u);
                        if (idx < MAXC) {
                            cand_rc[idx]  = ((uint32_t)rowr << 16) | (uint32_t)colr;
                            cand_val[idx] = v[r];
                        }
                    }
                }
                if (outF == nullptr) {
                    *reinterpret_cast<uint32_t*>(
                        outH + (size_t)row0 * Nstride + col) =
                        (sp[0] ? 0x3C00u : 0u) | ((sp[1] ? 0x3C00u : 0u) << 16);
                    *reinterpret_cast<uint32_t*>(
                        outH + (size_t)(row0 + 8) * Nstride + col) =
                        (sp[2] ? 0x3C00u : 0u) | ((sp[3] ? 0x3C00u : 0u) << 16);
                    *reinterpret_cast<uint16_t*>(
                        outI + (size_t)row0 * Nstride + col) =
                        (uint16_t)(sp[0] | (sp[1] << 8));
                    *reinterpret_cast<uint16_t*>(
                        outI + (size_t)(row0 + 8) * Nstride + col) =
                        (uint16_t)(sp[2] | (sp[3] << 8));
                } else if (col < Nstore) {
                    *reinterpret_cast<float2*>(
                        outF + (size_t)row0 * Nstore + col) =
                        make_float2((float)sp[0], (float)sp[1]);
                    *reinterpret_cast<float2*>(
                        outF + (size_t)(row0 + 8) * Nstore + col) =
                        make_float2((float)sp[2], (float)sp[3]);
                }
            }
        }
    }
}

// ---------------- fixup 1: int8-digit dot via dp4a ---------------------------
__global__ void fixmid_kernel(const uint32_t* __restrict__ crc,
                              const float* __restrict__ cval,
                              const uint32_t* __restrict__ cntp,
                              const int8_t* __restrict__ X,
                              const int8_t* __restrict__ Wm,
                              const float* __restrict__ e2,
                              const float* __restrict__ invS,
                              int K,
                              __half* __restrict__ outH,
                              int8_t* __restrict__ outI,
                              float* __restrict__ outF,
                              int NstrideH, int NstrideF,
                              uint32_t* __restrict__ crc_e,
                              uint32_t* __restrict__ cnt_e) {
    const int gw   = (blockIdx.x * blockDim.x + threadIdx.x) >> 5;
    const int lane = threadIdx.x & 31;
    const int nw   = (gridDim.x * blockDim.x) >> 5;
    uint32_t n = *cntp; if (n > MAXC) n = MAXC;
    const int K16 = K >> 4;
    for (uint32_t i = gw; i < n; i += nw) {
        const uint32_t e = crc[i];
        const int row = (int)(e >> 16);
        const int col = (int)(e & 0xFFFFu);
        int sc = 0;
        const uint4* xr = reinterpret_cast<const uint4*>(X)  + (size_t)row * K16;
        const uint4* mr = reinterpret_cast<const uint4*>(Wm) + (size_t)col * K16;
        for (int u = lane; u < K16; u += 32) {
            const uint4 xv = xr[u];
            const uint4 mv = mr[u];
            sc = dp4a_s(xv.x, mv.x, sc);
            sc = dp4a_s(xv.y, mv.y, sc);
            sc = dp4a_s(xv.z, mv.z, sc);
            sc = dp4a_s(xv.w, mv.w, sc);
        }
#pragma unroll
        for (int o = 16; o; o >>= 1) sc += __shfl_xor_sync(~0u, sc, o);
        if (lane == 0) {
            const float t = cval[i] + (float)sc * invS[col];
            if (fabsf(t - 1.0f) <= e2[col]) {
                const uint32_t idx = atomicAdd(cnt_e, 1u);
                if (idx < MAXC) crc_e[idx] = e;
            } else {
                const int spike = (t >= 1.0f);
                if (outF == nullptr) {
                    outH[(size_t)row * NstrideH + col] =
                        __ushort_as_half(spike ? (ushort)0x3C00 : (ushort)0);
                    outI[(size_t)row * NstrideH + col] = (int8_t)spike;
                } else {
                    outF[(size_t)row * NstrideF + col] = (float)spike;
                }
            }
        }
    }
}

// ---------------- fixup 2: exact fp32 dot -------------------------------------
__global__ void fixe_kernel(const uint32_t* __restrict__ crc,
                            const uint32_t* __restrict__ cntp,
                            const int8_t* __restrict__ X,
                            const float* __restrict__ W, int K,
                            __half* __restrict__ outH,
                            int8_t* __restrict__ outI,
                            float* __restrict__ outF,
                            int NstrideH, int NstrideF) {
    const int gw   = (blockIdx.x * blockDim.x + threadIdx.x) >> 5;
    const int lane = threadIdx.x & 31;
    const int nw   = (gridDim.x * blockDim.x) >> 5;
    uint32_t n = *cntp; if (n > MAXC) n = MAXC;
    for (uint32_t i = gw; i < n; i += nw) {
        const uint32_t e = crc[i];
        const int row = (int)(e >> 16);
        const int col = (int)(e & 0xFFFFu);
        float s = 0.0f;
        for (int k = lane; k < K; k += 32)
            s += (float)X[(size_t)row * K + k] * W[(size_t)col * K + k];
#pragma unroll
        for (int o = 16; o; o >>= 1) s += __shfl_xor_sync(~0u, s, o);
        if (lane == 0) {
            const int spike = (s >= 1.0f);
            if (outF == nullptr) {
                outH[(size_t)row * NstrideH + col] =
                    __ushort_as_half(spike ? (ushort)0x3C00 : (ushort)0);
                outI[(size_t)row * NstrideH + col] = (int8_t)spike;
            } else {
                outF[(size_t)row * NstrideF + col] = (float)spike;
            }
        }
    }
}

// ---------------- host launch --------------------------------------------------
extern "C" void kernel_launch(void* const* d_in, const int* in_sizes, int n_in,
                              void* d_out, int out_size) {
    const float* x  = (const float*)d_in[0];
    const float* W1 = (const float*)d_in[1];
    const float* W2 = (const float*)d_in[2];
    float* out = (float*)d_out;

    __half *xh, *w1h, *w2h, *s1h;
    int8_t *xi, *w1m, *w2m, *s1i;
    float *e1a, *e2a, *is1, *e1b, *e2b, *is2, *cv1, *cv2;
    uint32_t *crc1, *crc2, *crc1e, *crc2e, *cnt;
    cudaGetSymbolAddress((void**)&xh,  g_xh);
    cudaGetSymbolAddress((void**)&xi,  g_xi);
    cudaGetSymbolAddress((void**)&w1h, g_w1h);
    cudaGetSymbolAddress((void**)&w1m, g_w1m);
    cudaGetSymbolAddress((void**)&w2h, g_w2h);
    cudaGetSymbolAddress((void**)&w2m, g_w2m);
    cudaGetSymbolAddress((void**)&s1h, g_s1h);
    cudaGetSymbolAddress((void**)&s1i, g_s1i);
    cudaGetSymbolAddress((void**)&e1a, g_e1a);
    cudaGetSymbolAddress((void**)&e2a, g_e2a);
    cudaGetSymbolAddress((void**)&is1, g_is1);
    cudaGetSymbolAddress((void**)&e1b, g_e1b);
    cudaGetSymbolAddress((void**)&e2b, g_e2b);
    cudaGetSymbolAddress((void**)&is2, g_is2);
    cudaGetSymbolAddress((void**)&crc1,  g_crc1);
    cudaGetSymbolAddress((void**)&cv1,   g_cv1);
    cudaGetSymbolAddress((void**)&crc2,  g_crc2);
    cudaGetSymbolAddress((void**)&cv2,   g_cv2);
    cudaGetSymbolAddress((void**)&crc1e, g_crc1e);
    cudaGetSymbolAddress((void**)&crc2e, g_crc2e);
    cudaGetSymbolAddress((void**)&cnt,   g_cnt);

    const int smem1 = 1024 + 3 * (16384 + 128 * 128);   // BN=128: 99328
    const int smem2 = 1024 + 3 * (16384 + 64 * 128);    // BN= 64: 74752
    cudaFuncSetAttribute(spike_gemm_f16<128>,
                         cudaFuncAttributeMaxDynamicSharedMemorySize, smem1);
    cudaFuncSetAttribute(spike_gemm_f16<64>,
                         cudaFuncAttributeMaxDynamicSharedMemorySize, smem2);

    cvt_x_kernel<<<2048, 256>>>(x, xh, xi);   // also resets g_cnt
    split_w_kernel<<<FEAT / 8, 256>>>(W1, FEAT, FEAT, IN_K,
                                      w1h, w1m, e1a, e2a, is1);
    split_w_kernel<<<OUT_PAD / 8, 256>>>(W2, OUT_N, OUT_PAD, FEAT,
                                         w2h, w2m, e1b, e2b, is2);

    // Layer 1: s1 = (x @ W1^T >= 1)  -> dual fp16 + int8   (BN=128)
    {
        dim3 grid(FEAT / 128, B_ROWS / 128);   // (49, 32)
        spike_gemm_f16<128><<<grid, 128, smem1>>>(
            xh, w1h, e1a, s1h, s1i, nullptr,
            crc1, cv1, cnt + 0, IN_K, FEAT, FEAT);
    }
    fixmid_kernel<<<1024, 256>>>(crc1, cv1, cnt + 0, xi, w1m, e2a, is1, IN_K,
                                 s1h, s1i, nullptr, FEAT, 0, crc1e, cnt + 1);
    fixe_kernel<<<512, 256>>>(crc1e, cnt + 1, xi, W1, IN_K,
                              s1h, s1i, nullptr, FEAT, 0);

    // Layer 2: out = (s1 @ W2^T >= 1)  -> fp32   (BN=64, 256 CTAs = 1 wave)
    {
        dim3 grid(OUT_PAD / 64, B_ROWS / 128);  // (8, 32)
        spike_gemm_f16<64><<<grid, 128, smem2>>>(
            s1h, w2h, e1b, nullptr, nullptr, out,
            crc2, cv2, cnt + 2, FEAT, OUT_N, OUT_N);
    }
    fixmid_kernel<<<1024, 256>>>(crc2, cv2, cnt + 2, s1i, w2m, e2b, is2, FEAT,
                                 nullptr, nullptr, out, 0, OUT_N, crc2e, cnt + 3);
    fixe_kernel<<<512, 256>>>(crc2e, cnt + 3, s1i, W2, FEAT,
                              nullptr, nullptr, out, 0, OUT_N);
}

// round 16
// speedup vs baseline: 1.0487x; 1.0012x over previous
#include <cuda_runtime.h>
#include <cuda_fp16.h>
#include <cuda_bf16.h>
#include <cstdint>

// ---------------------------------------------------------------------------
// TempoJelly R16: single-split fp16 HMMA GEMM + int8-digit candidate fixup.
//   s2 = ((x @ W1^T >= 1) @ W2^T >= 1), x binary.
//
//  Numerics identical to R11/R12 (rel_err 0.0).
//  GEMM1: exact R12 config (128 thr, 2x2 warps of 64x64, BK=64, 3-stage) --
//    ptxas already software-pipelines it to the 255-reg ceiling; R13/R15
//    attempts to beat it both regressed.
//  R16 change: GEMM2 switched from BN=64 (98 tiny chunks, 8x A re-reads) to
//    BN=128 split-K2: grid (4,32,2) = 256 CTAs = one wave, halved L2
//    traffic, fp32 partials to scratch + combine kernel (threshold +
//    candidate capture there).
// ---------------------------------------------------------------------------

#define B_ROWS  4096
#define IN_K    3136
#define FEAT    6272
#define OUT_N   500
#define OUT_PAD 512
#define MAXC    (1 << 21)
#define MARGIN  3.0e-4f
#define KSPLIT2 (FEAT / 2)     // 3136 elements per K-split in layer 2

// ---------------- static scratch --------------------------------------------
__device__ __align__(16) __half  g_xh  [(size_t)B_ROWS * IN_K];
__device__ __align__(16) int8_t  g_xi  [(size_t)B_ROWS * IN_K];
__device__ __align__(16) __half  g_w1h [(size_t)FEAT * IN_K];
__device__ __align__(16) int8_t  g_w1m [(size_t)FEAT * IN_K];
__device__ __align__(16) __half  g_w2h [(size_t)OUT_PAD * FEAT];
__device__ __align__(16) int8_t  g_w2m [(size_t)OUT_PAD * FEAT];
__device__ __align__(16) __half  g_s1h [(size_t)B_ROWS * FEAT];
__device__ __align__(16) int8_t  g_s1i [(size_t)B_ROWS * FEAT];
__device__ __align__(16) float   g_part[2ULL * B_ROWS * OUT_PAD];   // 16MB
__device__ float g_e1a[FEAT],    g_e2a[FEAT],    g_is1[FEAT];
__device__ float g_e1b[OUT_PAD], g_e2b[OUT_PAD], g_is2[OUT_PAD];
__device__ uint32_t g_crc1[MAXC];
__device__ float    g_cv1 [MAXC];
__device__ uint32_t g_crc2[MAXC];
__device__ float    g_cv2 [MAXC];
__device__ uint32_t g_crc1e[MAXC];
__device__ uint32_t g_crc2e[MAXC];
__device__ uint32_t g_cnt[4];   // L1 cands, L1 final, L2 cands, L2 final

// ---------------- helpers ----------------------------------------------------
__device__ __forceinline__ uint32_t smem_u32(const void* p) {
    return (uint32_t)__cvta_generic_to_shared(p);
}
__device__ __forceinline__ uint32_t sw128(uint32_t off) {
    return off ^ ((off >> 3) & 0x70);
}
__device__ __forceinline__ int dp4a_s(uint32_t a, uint32_t b, int c) {
    return __dp4a((int)a, (int)b, c);
}

#define CP_ASYNC16(smaddr, gptr)                                               \
    asm volatile("cp.async.cg.shared.global [%0], [%1], 16;"                   \
                 :: "r"(smaddr), "l"(gptr))
#define CP_COMMIT() asm volatile("cp.async.commit_group;" ::: "memory")
#define CP_WAIT(n)  asm volatile("cp.async.wait_group %0;" :: "n"(n) : "memory")

#define LDSM_X4(r, addr)                                                       \
    asm volatile("ldmatrix.sync.aligned.m8n8.x4.shared.b16 {%0,%1,%2,%3}, [%4];" \
                 : "=r"((r)[0]), "=r"((r)[1]), "=r"((r)[2]), "=r"((r)[3])      \
                 : "r"(addr))

#define MMAF16(cc, aa, b0, b1)                                                 \
    asm volatile("mma.sync.aligned.m16n8k16.row.col.f32.f16.f16.f32 "          \
                 "{%0,%1,%2,%3},{%4,%5,%6,%7},{%8,%9},{%0,%1,%2,%3};"          \
                 : "+f"((cc)[0]), "+f"((cc)[1]), "+f"((cc)[2]), "+f"((cc)[3])  \
                 : "r"((aa)[0]), "r"((aa)[1]), "r"((aa)[2]), "r"((aa)[3]),     \
                   "r"(b0), "r"(b1))

// ---------------- prep kernels -----------------------------------------------
__global__ void cvt_x_kernel(const float* __restrict__ x,
                             __half* __restrict__ xh,
                             int8_t* __restrict__ xi) {
    if (blockIdx.x == 0 && threadIdx.x < 4) g_cnt[threadIdx.x] = 0;
    const size_t n4 = (size_t)B_ROWS * IN_K / 4;
    size_t i = (size_t)blockIdx.x * blockDim.x + threadIdx.x;
    const size_t stride = (size_t)gridDim.x * blockDim.x;
    for (; i < n4; i += stride) {
        const float4 v = reinterpret_cast<const float4*>(x)[i];
        const int b0 = (v.x != 0.0f), b1 = (v.y != 0.0f);
        const int b2 = (v.z != 0.0f), b3 = (v.w != 0.0f);
        const uint32_t h01 = (b0 ? 0x3C00u : 0u) | ((b1 ? 0x3C00u : 0u) << 16);
        const uint32_t h23 = (b2 ? 0x3C00u : 0u) | ((b3 ? 0x3C00u : 0u) << 16);
        reinterpret_cast<uint2*>(xh)[i] = make_uint2(h01, h23);
        reinterpret_cast<uchar4*>(xi)[i] =
            make_uchar4((unsigned char)b0, (unsigned char)b1,
                        (unsigned char)b2, (unsigned char)b3);
    }
}

__global__ void split_w_kernel(const float* __restrict__ W, int n_rows,
                               int rows_pad, int K,
                               __half* __restrict__ Wh,
                               int8_t* __restrict__ Wm,
                               float* __restrict__ e1,
                               float* __restrict__ e2,
                               float* __restrict__ invSo) {
    const int wid  = threadIdx.x >> 5;
    const int lane = threadIdx.x & 31;
    const int row  = blockIdx.x * (blockDim.x >> 5) + wid;
    if (row >= rows_pad) return;

    if (row >= n_rows) {
        for (int i = lane * 4; i < K; i += 128) {
            *reinterpret_cast<uint2*>(Wh + (size_t)row * K + i) = make_uint2(0, 0);
            *reinterpret_cast<char4*>(Wm + (size_t)row * K + i) = make_char4(0,0,0,0);
        }
        if (lane == 0) { e1[row] = -1.0f; e2[row] = -1.0f; invSo[row] = 0.0f; }
        return;
    }

    float s1 = 0.0f, mr = 0.0f;
    for (int i = lane * 4; i < K; i += 128) {
        const float4 v = *reinterpret_cast<const float4*>(W + (size_t)row * K + i);
        const float w[4] = {v.x, v.y, v.z, v.w};
        ushort hh[4];
#pragma unroll
        for (int j = 0; j < 4; j++) {
            const __half h = __float2half_rn(w[j]);
            const float r = w[j] - __half2float(h);
            s1 += fabsf(r);
            mr = fmaxf(mr, fabsf(r));
            hh[j] = __half_as_ushort(h);
        }
        *reinterpret_cast<uint2*>(Wh + (size_t)row * K + i) = make_uint2(
            (uint32_t)hh[0] | ((uint32_t)hh[1] << 16),
            (uint32_t)hh[2] | ((uint32_t)hh[3] << 16));
    }
#pragma unroll
    for (int o = 16; o; o >>= 1) {
        s1 += __shfl_xor_sync(~0u, s1, o);
        mr = fmaxf(mr, __shfl_xor_sync(~0u, mr, o));
    }
    const float S    = (mr > 0.0f) ? (127.0f / mr) : 1.0f;
    const float invS = (mr > 0.0f) ? (mr / 127.0f) : 0.0f;

    float s2 = 0.0f;
    for (int i = lane * 4; i < K; i += 128) {
        const float4 v = *reinterpret_cast<const float4*>(W + (size_t)row * K + i);
        const float w[4] = {v.x, v.y, v.z, v.w};
        char mm[4];
#pragma unroll
        for (int j = 0; j < 4; j++) {
            const __half h = __float2half_rn(w[j]);
            const float r = w[j] - __half2float(h);
            int q = __float2int_rn(r * S);
            q = max(-127, min(127, q));
            s2 += fabsf(fmaf(-(float)q, invS, r));
            mm[j] = (char)q;
        }
        *reinterpret_cast<char4*>(Wm + (size_t)row * K + i) =
            make_char4(mm[0], mm[1], mm[2], mm[3]);
    }
#pragma unroll
    for (int o = 16; o; o >>= 1) s2 += __shfl_xor_sync(~0u, s2, o);
    if (lane == 0) {
        e1[row] = s1 + MARGIN;
        e2[row] = s2 + MARGIN;
        invSo[row] = invS;
    }
}

// ---------------- fp16 HMMA GEMM: CTA 128x128, 128 thr, 2x2 warps, 3 stages ---
// Exact R12 mainloop. Modes:
//  partial != nullptr : raw fp32 partial write (split-K; blockIdx.z selects
//                       K-window of kSplit elements and partial slab).
//  else outF == nullptr : dual fp16+int8 spike outputs + candidates (L1)
//  else                 : fp32 spike output + candidates
__global__ __launch_bounds__(128, 2)
void spike_gemm_f16(const __half* __restrict__ A,
                    const __half* __restrict__ B,
                    const float* __restrict__ eps1,
                    __half* __restrict__ outH,
                    int8_t* __restrict__ outI,
                    float* __restrict__ outF,
                    float* __restrict__ partial,
                    uint32_t* __restrict__ cand_rc,
                    float* __restrict__ cand_val,
                    uint32_t* __restrict__ cnt,
                    int K8stride, int nchunks, int kSplit,
                    int Nstride, int Nstore) {
    constexpr int BN = 128;
    constexpr int WN = 64;
    constexpr int NB = 4;
    constexpr int STAGE = 16384 + BN * 128;
    constexpr int NSTG = 3;

    extern __shared__ char smem[];
    const uint32_t sbase = smem_u32(smem);
    const uint32_t data0 = (sbase + 1023u) & ~1023u;

    const int tid  = threadIdx.x;
    const int lane = tid & 31;
    const int wid  = tid >> 5;
    const int wm   = wid & 1;           // 2 warp-rows x 64
    const int wn   = wid >> 1;          // 2 warp-cols x 64
    const int bm   = blockIdx.y * 128;
    const int bn   = blockIdx.x * BN;
    const int kOffU = (blockIdx.z * kSplit) >> 3;   // uint4 K offset

    const int rA = lane & 15;
    const int kA = (lane >> 4) * 16;
    const int rB = ((lane >> 4) << 3) | (lane & 7);
    const int kB = ((lane >> 3) & 1) * 16;

    float acc[4][NB][8];
#pragma unroll
    for (int mt = 0; mt < 4; mt++)
#pragma unroll
        for (int nb = 0; nb < NB; nb++)
#pragma unroll
            for (int r = 0; r < 8; r++) acc[mt][nb][r] = 0.0f;

    auto load_chunk = [&](int ch) {
        uint32_t buf = data0 + (uint32_t)(ch % NSTG) * STAGE;
        const int k0u = kOffU + (ch << 3);
#pragma unroll
        for (int t = 0; t < 8; ++t) {            // A: 1024 uint4 / 128 thr
            const int u = tid + t * 128;
            const int row = u >> 3, ku = u & 7;
            const uint4* src = reinterpret_cast<const uint4*>(A)
                             + (size_t)(bm + row) * K8stride + k0u + ku;
            CP_ASYNC16(buf + sw128(row * 128 + ku * 16), src);
        }
#pragma unroll
        for (int t = 0; t < BN / 16; ++t) {      // B: 1024 uint4 / 128 thr
            const int u = tid + t * 128;
            const int row = u >> 3, ku = u & 7;
            const uint4* src = reinterpret_cast<const uint4*>(B)
                             + (size_t)(bn + row) * K8stride + k0u + ku;
            CP_ASYNC16(buf + 16384u + sw128(row * 128 + ku * 16), src);
        }
        CP_COMMIT();
    };

    load_chunk(0);
    load_chunk(1);

    for (int ch = 0; ch < nchunks; ++ch) {
        CP_WAIT(1);
        __syncthreads();

        if (ch + 2 < nchunks) load_chunk(ch + 2);
        else CP_COMMIT();

        const uint32_t buf = data0 + (uint32_t)(ch % NSTG) * STAGE;
#pragma unroll
        for (int ks = 0; ks < 4; ++ks) {
            uint32_t a[4][4];
#pragma unroll
            for (int mt = 0; mt < 4; mt++) {
                const uint32_t addr = buf
                    + sw128((wm * 64 + mt * 16 + rA) * 128 + ks * 32 + kA);
                LDSM_X4(a[mt], addr);
            }
#pragma unroll
            for (int nb = 0; nb < NB; nb++) {
                uint32_t b[4];
                const uint32_t addr = buf + 16384u
                    + sw128((wn * WN + nb * 16 + rB) * 128 + ks * 32 + kB);
                LDSM_X4(b, addr);
#pragma unroll
                for (int mt = 0; mt < 4; mt++) {
                    MMAF16(acc[mt][nb] + 0, a[mt], b[0], b[1]);
                    MMAF16(acc[mt][nb] + 4, a[mt], b[2], b[3]);
                }
            }
        }
    }

    // ---- epilogue ----
    if (partial) {   // split-K raw partial write (fp32, stride OUT_PAD)
        float* P = partial + (size_t)blockIdx.z * ((size_t)B_ROWS * OUT_PAD);
#pragma unroll
        for (int mt = 0; mt < 4; mt++) {
            const int row0 = bm + wm * 64 + mt * 16 + (lane >> 2);
#pragma unroll
            for (int nb = 0; nb < NB; nb++) {
#pragma unroll
                for (int h = 0; h < 2; h++) {
                    const int col = bn + wn * WN + nb * 16 + h * 8
                                  + (lane & 3) * 2;
                    const float* v = acc[mt][nb] + h * 4;
                    *reinterpret_cast<float2*>(P + (size_t)row0 * OUT_PAD + col) =
                        make_float2(v[0], v[1]);
                    *reinterpret_cast<float2*>(
                        P + (size_t)(row0 + 8) * OUT_PAD + col) =
                        make_float2(v[2], v[3]);
                }
            }
        }
        return;
    }

    float ev[NB][2][2];
#pragma unroll
    for (int nb = 0; nb < NB; nb++)
#pragma unroll
        for (int h = 0; h < 2; h++) {
            const int col = bn + wn * WN + nb * 16 + h * 8 + (lane & 3) * 2;
            ev[nb][h][0] = eps1[col];
            ev[nb][h][1] = eps1[col + 1];
        }

#pragma unroll
    for (int mt = 0; mt < 4; mt++) {
        const int row0 = bm + wm * 64 + mt * 16 + (lane >> 2);
#pragma unroll
        for (int nb = 0; nb < NB; nb++) {
#pragma unroll
            for (int h = 0; h < 2; h++) {
                const int col = bn + wn * WN + nb * 16 + h * 8 + (lane & 3) * 2;
                const float* v = acc[mt][nb] + h * 4;
                int sp[4];
#pragma unroll
                for (int r = 0; r < 4; r++) {
                    sp[r] = (v[r] >= 1.0f);
                    const int colr = col + (r & 1);
                    if (fabsf(v[r] - 1.0f) <= ev[nb][h][r & 1] && colr < Nstore) {
                        const int rowr = row0 + (r >> 1) * 8;
                        const uint32_t idx = atomicAdd(cnt, 1u);
                        if (idx < MAXC) {
                            cand_rc[idx]  = ((uint32_t)rowr << 16) | (uint32_t)colr;
                            cand_val[idx] = v[r];
                        }
                    }
                }
                if (outF == nullptr) {
                    *reinterpret_cast<uint32_t*>(
                        outH + (size_t)row0 * Nstride + col) =
                        (sp[0] ? 0x3C00u : 0u) | ((sp[1] ? 0x3C00u : 0u) << 16);
                    *reinterpret_cast<uint32_t*>(
                        outH + (size_t)(row0 + 8) * Nstride + col) =
                        (sp[2] ? 0x3C00u : 0u) | ((sp[3] ? 0x3C00u : 0u) << 16);
                    *reinterpret_cast<uint16_t*>(
                        outI + (size_t)row0 * Nstride + col) =
                        (uint16_t)(sp[0] | (sp[1] << 8));
                    *reinterpret_cast<uint16_t*>(
                        outI + (size_t)(row0 + 8) * Nstride + col) =
                        (uint16_t)(sp[2] | (sp[3] << 8));
                } else if (col < Nstore) {
                    *reinterpret_cast<float2*>(
                        outF + (size_t)row0 * Nstore + col) =
                        make_float2((float)sp[0], (float)sp[1]);
                    *reinterpret_cast<float2*>(
                        outF + (size_t)(row0 + 8) * Nstore + col) =
                        make_float2((float)sp[2], (float)sp[3]);
                }
            }
        }
    }
}

// ---------------- split-K combine: t = p0 + p1, threshold + candidates --------
__global__ void combine2_kernel(const float* __restrict__ part,
                                const float* __restrict__ e1,
                                float* __restrict__ out,
                                uint32_t* __restrict__ cand_rc,
                                float* __restrict__ cand_val,
                                uint32_t* __restrict__ cnt) {
    const size_t idx = (size_t)blockIdx.x * blockDim.x + threadIdx.x;
    if (idx >= (size_t)B_ROWS * OUT_PAD) return;
    const int row = (int)(idx >> 9);        // OUT_PAD = 512
    const int col = (int)(idx & 511);
    const float t = part[idx] + part[idx + (size_t)B_ROWS * OUT_PAD];
    if (col < OUT_N) {
        out[(size_t)row * OUT_N + col] = (t >= 1.0f) ? 1.0f : 0.0f;
        if (fabsf(t - 1.0f) <= e1[col]) {
            const uint32_t i = atomicAdd(cnt, 1u);
            if (i < MAXC) {
                cand_rc[i]  = ((uint32_t)row << 16) | (uint32_t)col;
                cand_val[i] = t;
            }
        }
    }
}

// ---------------- fixup 1: int8-digit dot via dp4a ---------------------------
__global__ void fixmid_kernel(const uint32_t* __restrict__ crc,
                              const float* __restrict__ cval,
                              const uint32_t* __restrict__ cntp,
                              const int8_t* __restrict__ X,
                              const int8_t* __restrict__ Wm,
                              const float* __restrict__ e2,
                              const float* __restrict__ invS,
                              int K,
                              __half* __restrict__ outH,
                              int8_t* __restrict__ outI,
                              float* __restrict__ outF,
                              int NstrideH, int NstrideF,
                              uint32_t* __restrict__ crc_e,
                              uint32_t* __restrict__ cnt_e) {
    const int gw   = (blockIdx.x * blockDim.x + threadIdx.x) >> 5;
    const int lane = threadIdx.x & 31;
    const int nw   = (gridDim.x * blockDim.x) >> 5;
    uint32_t n = *cntp; if (n > MAXC) n = MAXC;
    const int K16 = K >> 4;
    for (uint32_t i = gw; i < n; i += nw) {
        const uint32_t e = crc[i];
        const int row = (int)(e >> 16);
        const int col = (int)(e & 0xFFFFu);
        int sc = 0;
        const uint4* xr = reinterpret_cast<const uint4*>(X)  + (size_t)row * K16;
        const uint4* mr = reinterpret_cast<const uint4*>(Wm) + (size_t)col * K16;
        for (int u = lane; u < K16; u += 32) {
            const uint4 xv = xr[u];
            const uint4 mv = mr[u];
            sc = dp4a_s(xv.x, mv.x, sc);
            sc = dp4a_s(xv.y, mv.y, sc);
            sc = dp4a_s(xv.z, mv.z, sc);
            sc = dp4a_s(xv.w, mv.w, sc);
        }
#pragma unroll
        for (int o = 16; o; o >>= 1) sc += __shfl_xor_sync(~0u, sc, o);
        if (lane == 0) {
            const float t = cval[i] + (float)sc * invS[col];
            if (fabsf(t - 1.0f) <= e2[col]) {
                const uint32_t idx = atomicAdd(cnt_e, 1u);
                if (idx < MAXC) crc_e[idx] = e;
            } else {
                const int spike = (t >= 1.0f);
                if (outF == nullptr) {
                    outH[(size_t)row * NstrideH + col] =
                        __ushort_as_half(spike ? (ushort)0x3C00 : (ushort)0);
                    outI[(size_t)row * NstrideH + col] = (int8_t)spike;
                } else {
                    outF[(size_t)row * NstrideF + col] = (float)spike;
                }
            }
        }
    }
}

// ---------------- fixup 2: exact fp32 dot -------------------------------------
__global__ void fixe_kernel(const uint32_t* __restrict__ crc,
                            const uint32_t* __restrict__ cntp,
                            const int8_t* __restrict__ X,
                            const float* __restrict__ W, int K,
                            __half* __restrict__ outH,
                            int8_t* __restrict__ outI,
                            float* __restrict__ outF,
                            int NstrideH, int NstrideF) {
    const int gw   = (blockIdx.x * blockDim.x + threadIdx.x) >> 5;
    const int lane = threadIdx.x & 31;
    const int nw   = (gridDim.x * blockDim.x) >> 5;
    uint32_t n = *cntp; if (n > MAXC) n = MAXC;
    for (uint32_t i = gw; i < n; i += nw) {
        const uint32_t e = crc[i];
        const int row = (int)(e >> 16);
        const int col = (int)(e & 0xFFFFu);
        float s = 0.0f;
        for (int k = lane; k < K; k += 32)
            s += (float)X[(size_t)row * K + k] * W[(size_t)col * K + k];
#pragma unroll
        for (int o = 16; o; o >>= 1) s += __shfl_xor_sync(~0u, s, o);
        if (lane == 0) {
            const int spike = (s >= 1.0f);
            if (outF == nullptr) {
                outH[(size_t)row * NstrideH + col] =
                    __ushort_as_half(spike ? (ushort)0x3C00 : (ushort)0);
                outI[(size_t)row * NstrideH + col] = (int8_t)spike;
            } else {
                outF[(size_t)row * NstrideF + col] = (float)spike;
            }
        }
    }
}

// ---------------- host launch --------------------------------------------------
extern "C" void kernel_launch(void* const* d_in, const int* in_sizes, int n_in,
                              void* d_out, int out_size) {
    const float* x  = (const float*)d_in[0];
    const float* W1 = (const float*)d_in[1];
    const float* W2 = (const float*)d_in[2];
    float* out = (float*)d_out;

    __half *xh, *w1h, *w2h, *s1h;
    int8_t *xi, *w1m, *w2m, *s1i;
    float *part, *e1a, *e2a, *is1, *e1b, *e2b, *is2, *cv1, *cv2;
    uint32_t *crc1, *crc2, *crc1e, *crc2e, *cnt;
    cudaGetSymbolAddress((void**)&xh,  g_xh);
    cudaGetSymbolAddress((void**)&xi,  g_xi);
    cudaGetSymbolAddress((void**)&w1h, g_w1h);
    cudaGetSymbolAddress((void**)&w1m, g_w1m);
    cudaGetSymbolAddress((void**)&w2h, g_w2h);
    cudaGetSymbolAddress((void**)&w2m, g_w2m);
    cudaGetSymbolAddress((void**)&s1h, g_s1h);
    cudaGetSymbolAddress((void**)&s1i, g_s1i);
    cudaGetSymbolAddress((void**)&part, g_part);
    cudaGetSymbolAddress((void**)&e1a, g_e1a);
    cudaGetSymbolAddress((void**)&e2a, g_e2a);
    cudaGetSymbolAddress((void**)&is1, g_is1);
    cudaGetSymbolAddress((void**)&e1b, g_e1b);
    cudaGetSymbolAddress((void**)&e2b, g_e2b);
    cudaGetSymbolAddress((void**)&is2, g_is2);
    cudaGetSymbolAddress((void**)&crc1,  g_crc1);
    cudaGetSymbolAddress((void**)&cv1,   g_cv1);
    cudaGetSymbolAddress((void**)&crc2,  g_crc2);
    cudaGetSymbolAddress((void**)&cv2,   g_cv2);
    cudaGetSymbolAddress((void**)&crc1e, g_crc1e);
    cudaGetSymbolAddress((void**)&crc2e, g_crc2e);
    cudaGetSymbolAddress((void**)&cnt,   g_cnt);

    const int smem1 = 1024 + 3 * (16384 + 128 * 128);   // 99328
    cudaFuncSetAttribute(spike_gemm_f16,
                         cudaFuncAttributeMaxDynamicSharedMemorySize, smem1);

    cvt_x_kernel<<<2048, 256>>>(x, xh, xi);   // also resets g_cnt
    split_w_kernel<<<FEAT / 8, 256>>>(W1, FEAT, FEAT, IN_K,
                                      w1h, w1m, e1a, e2a, is1);
    split_w_kernel<<<OUT_PAD / 8, 256>>>(W2, OUT_N, OUT_PAD, FEAT,
                                         w2h, w2m, e1b, e2b, is2);

    // Layer 1: s1 = (x @ W1^T >= 1)  -> dual fp16 + int8
    {
        dim3 grid(FEAT / 128, B_ROWS / 128, 1);   // (49, 32)
        spike_gemm_f16<<<grid, 128, smem1>>>(
            xh, w1h, e1a, s1h, s1i, nullptr, nullptr,
            crc1, cv1, cnt + 0, IN_K / 8, IN_K / 64, 0, FEAT, FEAT);
    }
    fixmid_kernel<<<1024, 256>>>(crc1, cv1, cnt + 0, xi, w1m, e2a, is1, IN_K,
                                 s1h, s1i, nullptr, FEAT, 0, crc1e, cnt + 1);
    fixe_kernel<<<512, 256>>>(crc1e, cnt + 1, xi, W1, IN_K,
                              s1h, s1i, nullptr, FEAT, 0);

    // Layer 2: split-K2 partials (BN=128, grid (4,32,2) = 256 CTAs, one wave)
    {
        dim3 grid(OUT_PAD / 128, B_ROWS / 128, 2);   // (4, 32, 2)
        spike_gemm_f16<<<grid, 128, smem1>>>(
            s1h, w2h, e1b, nullptr, nullptr, nullptr, part,
            nullptr, nullptr, nullptr, FEAT / 8, KSPLIT2 / 64, KSPLIT2,
            OUT_PAD, OUT_N);
    }
    // Combine partials -> spikes + candidates
    {
        const int total = B_ROWS * OUT_PAD;
        combine2_kernel<<<(total + 255) / 256, 256>>>(
            part, e1b, out, crc2, cv2, cnt + 2);
    }
    fixmid_kernel<<<1024, 256>>>(crc2, cv2, cnt + 2, s1i, w2m, e2b, is2, FEAT,
                                 nullptr, nullptr, out, 0, OUT_N, crc2e, cnt + 3);
    fixe_kernel<<<512, 256>>>(crc2e, cnt + 3, s1i, W2, FEAT,
                              nullptr, nullptr, out, 0, OUT_N);
}